// round 6
// baseline (speedup 1.0000x reference)
#include <cuda_runtime.h>
#include <cuda_bf16.h>
#include <float.h>
#include <math.h>

// Problem constants
#define B 64
#define IN_DIM 256
#define H 512
#define M 64
#define N 8192
#define GJ 2048          // 4*H
#define KPART 768        // inp + h K-columns
#define DTILE 128        // rows per dot/mread/mout tile (64 tiles per batch)

// Output layout (floats)
#define OUT_C_OFF (B*H)
#define OUT_R_OFF (2*B*H)
#define OUT_W_OFF (2*B*H + B*N)
#define OUT_M_OFF (2*B*H + 2*B*N)

// Scratch (static device globals — no allocation)
__device__ float g_k[B*M];
__device__ __align__(128) float g_par[B*32];
__device__ float g_logit[B*N];
__device__ float g_mpart[B*64*M];
__device__ float g_Mread[B*M];
__device__ float g_gatesT[GJ*B];              // partial gates [j][b]
__device__ float g_ea[B*2*M];

// Flags/counters (zero-init; each kernel resets the OTHER kernel's)
__device__ int fA[B];       // KA ctrl  -> KA dot          (reset by KB)
__device__ int dcntA[B];    // KA dot   -> KA address      (reset by KB)
__device__ int fB[B];       // KA addr  -> KA mread        (reset by KB)
__device__ int mcnt[B];     // KA mread chunk counter      (reset by KB)
__device__ int ctrC;        // KB fixup -> KB controller   (reset by KA)
__device__ int fC[B];       // KB ctrl  -> KB dot          (reset by KA)
__device__ int dcntB[B];    // KB dot   -> KB address      (reset by KA)
__device__ int fD[B];       // KB addr  -> KB mout         (reset by KA)

__device__ __forceinline__ float sigf(float x) { return 1.0f / (1.0f + __expf(-x)); }

__device__ __forceinline__ void spin_on(int* f)
{
    if (threadIdx.x == 0) {
        while (atomicAdd(f, 0) == 0) __nanosleep(64);
    }
    __syncthreads();
    __threadfence();
}

__device__ __forceinline__ void spin_count(int* c, int target)
{
    if (threadIdx.x == 0) {
        while (atomicAdd(c, 0) < target) __nanosleep(64);
    }
    __syncthreads();
    __threadfence();
}

__device__ __forceinline__ void release(int* f)
{
    __threadfence();
    __syncthreads();
    if (threadIdx.x == 0) atomicExch(f, 1);
}

// ---------------------------------------------------------------------------
// Block reductions (256 threads, 8 warps)
// ---------------------------------------------------------------------------
__device__ __forceinline__ float bsum(float v, float* red)
{
    #pragma unroll
    for (int o = 16; o; o >>= 1) v += __shfl_xor_sync(0xffffffffu, v, o);
    int t = threadIdx.x;
    if ((t & 31) == 0) red[t >> 5] = v;
    __syncthreads();
    if (t < 8) {
        v = red[t];
        #pragma unroll
        for (int o = 4; o; o >>= 1) v += __shfl_xor_sync(0xffu, v, o);
        if (t == 0) red[0] = v;
    }
    __syncthreads();
    float r = red[0];
    __syncthreads();
    return r;
}

__device__ __forceinline__ float bmax(float v, float* red)
{
    #pragma unroll
    for (int o = 16; o; o >>= 1) v = fmaxf(v, __shfl_xor_sync(0xffffffffu, v, o));
    int t = threadIdx.x;
    if ((t & 31) == 0) red[t >> 5] = v;
    __syncthreads();
    if (t < 8) {
        v = red[t];
        #pragma unroll
        for (int o = 4; o; o >>= 1) v = fmaxf(v, __shfl_xor_sync(0xffu, v, o));
        if (t == 0) red[0] = v;
    }
    __syncthreads();
    float r = red[0];
    __syncthreads();
    return r;
}

// ---------------------------------------------------------------------------
// Controller (one block per batch, 256 threads)
// ---------------------------------------------------------------------------
__device__ void controller_dev(int b, const float* __restrict__ hstate,
                               const float* __restrict__ kw, const float* __restrict__ kb,
                               const float* __restrict__ cw, const float* __restrict__ cb,
                               const float* __restrict__ sw, const float* __restrict__ sb,
                               const float* __restrict__ ww, const float* __restrict__ wb)
{
    int t = threadIdx.x;
    __shared__ float hs[H];
    __shared__ float ks[M];
    __shared__ float cvs[3];
    __shared__ float ss[3];

    for (int i = t; i < H; i += 256) hs[i] = hstate[(size_t)b*H + i];
    __syncthreads();

    if (t < M) {
        const float4* w4 = (const float4*)(kw + (size_t)t * H);
        float acc = kb[t];
        #pragma unroll 8
        for (int q = 0; q < H/4; q++) {
            float4 wv = w4[q]; int j = q*4;
            acc += wv.x*hs[j] + wv.y*hs[j+1] + wv.z*hs[j+2] + wv.w*hs[j+3];
        }
        ks[t] = tanhf(acc);
    } else if (t < M + 3) {
        int r = t - M;
        const float4* w4 = (const float4*)(cw + (size_t)r * H);
        float acc = cb[r];
        for (int q = 0; q < H/4; q++) {
            float4 wv = w4[q]; int j = q*4;
            acc += wv.x*hs[j] + wv.y*hs[j+1] + wv.z*hs[j+2] + wv.w*hs[j+3];
        }
        cvs[r] = acc;
    } else if (t < M + 6) {
        int r = t - M - 3;
        const float4* w4 = (const float4*)(sw + (size_t)r * H);
        float acc = sb[r];
        for (int q = 0; q < H/4; q++) {
            float4 wv = w4[q]; int j = q*4;
            acc += wv.x*hs[j] + wv.y*hs[j+1] + wv.z*hs[j+2] + wv.w*hs[j+3];
        }
        ss[r] = acc;
    } else if (ww != nullptr && t >= 70 && t < 70 + 2*M) {
        int r = t - 70;
        const float4* w4 = (const float4*)(ww + (size_t)r * H);
        float acc = wb[r];
        for (int q = 0; q < H/4; q++) {
            float4 wv = w4[q]; int j = q*4;
            acc += wv.x*hs[j] + wv.y*hs[j+1] + wv.z*hs[j+2] + wv.w*hs[j+3];
        }
        g_ea[b*2*M + r] = (r < M) ? sigf(acc) : acc;
    }
    __syncthreads();

    if (t < M) g_k[b*M + t] = ks[t];
    if (t == 0) {
        float mx = fmaxf(ss[0], fmaxf(ss[1], ss[2]));
        float e0 = __expf(ss[0]-mx), e1 = __expf(ss[1]-mx), e2 = __expf(ss[2]-mx);
        float tot = e0 + e1 + e2;
        float nk = 0.0f;
        for (int j = 0; j < M; j++) nk += ks[j]*ks[j];
        g_par[b*32 + 0] = fmaxf(cvs[0], 0.0f) + 0.0001f;
        g_par[b*32 + 1] = sigf(cvs[1]);
        g_par[b*32 + 2] = fmaxf(cvs[2], 0.0f) + 1.0001f;
        g_par[b*32 + 3] = e0/tot;
        g_par[b*32 + 4] = e1/tot;
        g_par[b*32 + 5] = e2/tot;
        g_par[b*32 + 6] = nk;
    }
}

// ---------------------------------------------------------------------------
// GEMM-partial: gatesT[j][b] = bias_j + inp[b]@W_ih[j,:256] + h[b]@W_hh[j,:]
// ---------------------------------------------------------------------------
__device__ void gemm_partial(int gbid,
                             const float* __restrict__ inp,
                             const float* __restrict__ h,
                             const float* __restrict__ W_ih,
                             const float* __restrict__ b_ih,
                             const float* __restrict__ W_hh,
                             const float* __restrict__ b_hh)
{
    __shared__ float Xs[64][33];
    __shared__ float Ws[32][33];
    int t  = threadIdx.x;
    int tx = t & 15;
    int ty = t >> 4;
    int jbase = gbid * 32;
    int lrow = t >> 2;
    int lcol = (t & 3) * 8;
    int wrow = t >> 3;
    int wcol = (t & 7) * 4;

    float acc[4][2];
    #pragma unroll
    for (int i = 0; i < 4; i++) { acc[i][0] = 0.0f; acc[i][1] = 0.0f; }

    for (int kc = 0; kc < KPART/32; kc++) {
        int k0 = kc * 32;
        const float* xsrc = (k0 < IN_DIM)
            ? (inp + (size_t)lrow*IN_DIM + k0 + lcol)
            : (h   + (size_t)lrow*H + (k0 - IN_DIM) + lcol);
        float4 xa = *(const float4*)xsrc;
        float4 xb = *(const float4*)(xsrc + 4);
        Xs[lrow][lcol+0]=xa.x; Xs[lrow][lcol+1]=xa.y; Xs[lrow][lcol+2]=xa.z; Xs[lrow][lcol+3]=xa.w;
        Xs[lrow][lcol+4]=xb.x; Xs[lrow][lcol+5]=xb.y; Xs[lrow][lcol+6]=xb.z; Xs[lrow][lcol+7]=xb.w;
        const float* wsrc = (k0 < IN_DIM)
            ? (W_ih + (size_t)(jbase + wrow)*(IN_DIM + M) + k0 + wcol)
            : (W_hh + (size_t)(jbase + wrow)*H + (k0 - IN_DIM) + wcol);
        float4 wa = *(const float4*)wsrc;
        Ws[wrow][wcol+0]=wa.x; Ws[wrow][wcol+1]=wa.y; Ws[wrow][wcol+2]=wa.z; Ws[wrow][wcol+3]=wa.w;
        __syncthreads();
        #pragma unroll
        for (int k = 0; k < 32; k++) {
            float xv[4], wv[2];
            #pragma unroll
            for (int i = 0; i < 4; i++) xv[i] = Xs[tx*4 + i][k];
            wv[0] = Ws[ty*2 + 0][k];
            wv[1] = Ws[ty*2 + 1][k];
            #pragma unroll
            for (int i = 0; i < 4; i++) {
                acc[i][0] += xv[i] * wv[0];
                acc[i][1] += xv[i] * wv[1];
            }
        }
        __syncthreads();
    }
    #pragma unroll
    for (int jj = 0; jj < 2; jj++) {
        int j = jbase + ty*2 + jj;
        float bias = b_ih[j] + b_hh[j];
        #pragma unroll
        for (int i = 0; i < 4; i++)
            g_gatesT[(size_t)j*B + (tx*4 + i)] = acc[i][jj] + bias;
    }
}

// ---------------------------------------------------------------------------
// Dot tile (128 rows): prefetch -> spin -> compute -> bump per-batch counter
// ---------------------------------------------------------------------------
__device__ void dot_tile(const float* __restrict__ Mem, int b, int xt,
                         int* flags, int* dcnt)
{
    int t = threadIdx.x;
    int lane8 = t & 7, rowp = t >> 3;

    float4 pf[8];
    size_t base = ((size_t)b*N + xt*DTILE)*M;
    #pragma unroll
    for (int it = 0; it < 4; it++) {
        const float4* p = (const float4*)(Mem + base + (size_t)(it*32 + rowp)*M) + lane8*2;
        pf[it*2]   = p[0];
        pf[it*2+1] = p[1];
    }

    spin_on(&flags[b]);

    int m0 = lane8 * 8;
    float4 ka = *(const float4*)(g_k + b*M + m0);
    float4 kb4 = *(const float4*)(g_k + b*M + m0 + 4);
    float beta = g_par[b*32 + 0];
    float nk   = g_par[b*32 + 6];

    #pragma unroll
    for (int it = 0; it < 4; it++) {
        float4 v0 = pf[it*2], v1 = pf[it*2+1];
        float d  = v0.x*ka.x + v0.y*ka.y + v0.z*ka.z + v0.w*ka.w
                 + v1.x*kb4.x + v1.y*kb4.y + v1.z*kb4.z + v1.w*kb4.w;
        float nm = v0.x*v0.x + v0.y*v0.y + v0.z*v0.z + v0.w*v0.w
                 + v1.x*v1.x + v1.y*v1.y + v1.z*v1.z + v1.w*v1.w;
        #pragma unroll
        for (int o = 4; o; o >>= 1) {
            d  += __shfl_xor_sync(0xffffffffu, d,  o);
            nm += __shfl_xor_sync(0xffffffffu, nm, o);
        }
        if (lane8 == 0) g_logit[(size_t)b*N + xt*DTILE + it*32 + rowp] = beta * d / (nm * nk);
    }

    __threadfence();
    __syncthreads();
    if (t == 0) atomicAdd(&dcnt[b], 1);
}

// ---------------------------------------------------------------------------
// Address (256 threads)
// ---------------------------------------------------------------------------
__device__ void address_dev(int b, const float* __restrict__ head_prev,
                            float* __restrict__ out_head)
{
    __shared__ float A[N];       // 32KB
    __shared__ float red[8];
    int t = threadIdx.x;
    float g     = g_par[b*32 + 1];
    float gamma = g_par[b*32 + 2];
    float s0    = g_par[b*32 + 3];
    float s1    = g_par[b*32 + 4];
    float s2    = g_par[b*32 + 5];

    const float* lg = g_logit + (size_t)b*N;
    float vmax = -FLT_MAX;
    #pragma unroll
    for (int i = 0; i < 32; i++) {
        float v = lg[i*256 + t];
        A[i*256 + t] = v;
        vmax = fmaxf(vmax, v);
    }
    vmax = bmax(vmax, red);

    float lsum = 0.0f;
    #pragma unroll
    for (int i = 0; i < 32; i++) {
        int idx = i*256 + t;
        float e = __expf(A[idx] - vmax);
        A[idx] = e;
        lsum += e;
    }
    float inv = 1.0f / bsum(lsum, red);

    const float* hp = head_prev + (size_t)b*N;
    #pragma unroll
    for (int i = 0; i < 32; i++) {
        int idx = i*256 + t;
        A[idx] = g * (A[idx] * inv) + (1.0f - g) * hp[idx];
    }
    __syncthreads();

    float p[32];
    float psum = 0.0f;
    #pragma unroll
    for (int i = 0; i < 32; i++) {
        int idx = i*256 + t;
        float o = s0 * A[(idx + N - 2) & (N-1)]
                + s1 * A[(idx + N - 1) & (N-1)]
                + s2 * A[idx];
        p[i] = __powf(o, gamma);
        psum += p[i];
    }
    float inv2 = 1.0f / bsum(psum, red);
    #pragma unroll
    for (int i = 0; i < 32; i++)
        out_head[(size_t)b*N + i*256 + t] = p[i] * inv2;
}

// ---------------------------------------------------------------------------
// M_read chunk (128 rows): prefetch -> spin -> weighted sum -> partials;
// last chunk per batch reduces to g_Mread[b].
// ---------------------------------------------------------------------------
__device__ void mread_chunk(const float* __restrict__ Mem,
                            const float* __restrict__ rhead, int b, int ch)
{
    int t = threadIdx.x;
    int lane8 = t & 7, rowp = t >> 3;

    float4 pf[8];
    size_t base = ((size_t)b*N + ch*DTILE)*M;
    #pragma unroll
    for (int it = 0; it < 4; it++) {
        const float4* p = (const float4*)(Mem + base + (size_t)(it*32 + rowp)*M) + lane8*2;
        pf[it*2]   = p[0];
        pf[it*2+1] = p[1];
    }

    spin_on(&fB[b]);

    float a0=0,a1=0,a2=0,a3=0,a4=0,a5=0,a6=0,a7=0;
    const float* hp = rhead + (size_t)b*N + ch*DTILE;
    #pragma unroll
    for (int it = 0; it < 4; it++) {
        float r = hp[it*32 + rowp];
        float4 v0 = pf[it*2], v1 = pf[it*2+1];
        a0 += r*v0.x; a1 += r*v0.y; a2 += r*v0.z; a3 += r*v0.w;
        a4 += r*v1.x; a5 += r*v1.y; a6 += r*v1.z; a7 += r*v1.w;
    }

    __shared__ float sdata[256*8];
    float* s = sdata + t*8;
    s[0]=a0; s[1]=a1; s[2]=a2; s[3]=a3; s[4]=a4; s[5]=a5; s[6]=a6; s[7]=a7;
    __syncthreads();
    if (t < 64) {
        int lg2 = t >> 3, j = t & 7;
        float acc = 0.0f;
        #pragma unroll
        for (int rw = 0; rw < 32; rw++) acc += sdata[((rw<<3) | lg2)*8 + j];
        g_mpart[((size_t)b*64 + ch)*M + lg2*8 + j] = acc;
    }

    __threadfence();
    __syncthreads();
    __shared__ int lastf;
    if (t == 0) lastf = (atomicAdd(&mcnt[b], 1) == 63) ? 1 : 0;
    __syncthreads();
    if (lastf) {
        __threadfence();
        int k = t & 63, q = t >> 6;
        float a = 0.0f;
        #pragma unroll
        for (int p = 0; p < 16; p++)
            a += g_mpart[((size_t)b*64 + q*16 + p)*M + k];
        __shared__ float sr[256];
        sr[t] = a;
        __syncthreads();
        if (t < 64) g_Mread[b*M + t] = sr[t] + sr[64+t] + sr[128+t] + sr[192+t];
    }
}

// ---------------------------------------------------------------------------
// Fixup + LSTM: gates = gatesT + M_read @ W_mid; h_new/c_new (4 h per block)
// ---------------------------------------------------------------------------
__device__ void fixup_dev(int blk, const float* __restrict__ W_ih,
                          const float* __restrict__ c,
                          float* __restrict__ out_h, float* __restrict__ out_c)
{
    __shared__ float Wm[16][65];
    __shared__ float Mr[64][65];
    int t = threadIdx.x;
    int hbase = blk * 4;

    {
        int r = t >> 4;
        int off = (t & 15) * 4;
        int gate = r >> 2, hloc = r & 3;
        float4 v = *(const float4*)(W_ih + (size_t)(gate*H + hbase + hloc)*(IN_DIM + M) + IN_DIM + off);
        Wm[r][off+0]=v.x; Wm[r][off+1]=v.y; Wm[r][off+2]=v.z; Wm[r][off+3]=v.w;
    }
    {
        int row = t >> 2;
        int col = (t & 3) * 16;
        const float4* src = (const float4*)(g_Mread + (size_t)row*M + col);
        float4 v0 = src[0], v1 = src[1], v2 = src[2], v3 = src[3];
        Mr[row][col+ 0]=v0.x; Mr[row][col+ 1]=v0.y; Mr[row][col+ 2]=v0.z; Mr[row][col+ 3]=v0.w;
        Mr[row][col+ 4]=v1.x; Mr[row][col+ 5]=v1.y; Mr[row][col+ 6]=v1.z; Mr[row][col+ 7]=v1.w;
        Mr[row][col+ 8]=v2.x; Mr[row][col+ 9]=v2.y; Mr[row][col+10]=v2.z; Mr[row][col+11]=v2.w;
        Mr[row][col+12]=v3.x; Mr[row][col+13]=v3.y; Mr[row][col+14]=v3.z; Mr[row][col+15]=v3.w;
    }
    __syncthreads();

    int b = t & 63;
    int hloc = t >> 6;
    int hh = hbase + hloc;

    float acc[4];
    #pragma unroll
    for (int g4 = 0; g4 < 4; g4++)
        acc[g4] = g_gatesT[(size_t)(g4*H + hh)*B + b];
    #pragma unroll 8
    for (int k = 0; k < M; k++) {
        float m = Mr[b][k];
        #pragma unroll
        for (int g4 = 0; g4 < 4; g4++) acc[g4] += m * Wm[g4*4 + hloc][k];
    }

    float cn = sigf(acc[1]) * c[(size_t)b*H + hh] + sigf(acc[0]) * tanhf(acc[2]);
    float hn = sigf(acc[3]) * tanhf(cn);
    out_c[(size_t)b*H + hh] = cn;
    out_h[(size_t)b*H + hh] = hn;

    __threadfence();
    __syncthreads();
    if (t == 0) atomicAdd(&ctrC, 1);
}

// ---------------------------------------------------------------------------
// M_out tile (128 rows): prefetch -> spin -> update (streaming stores)
// ---------------------------------------------------------------------------
__device__ void mout_tile(const float* __restrict__ Mem,
                          const float* __restrict__ whead,
                          float* __restrict__ outM, int b, int xt)
{
    int t = threadIdx.x;
    int lane8 = t & 7, rowp = t >> 3;

    float4 pf[8];
    size_t base = ((size_t)b*N + xt*DTILE)*M;
    #pragma unroll
    for (int it = 0; it < 4; it++) {
        const float4* p = (const float4*)(Mem + base + (size_t)(it*32 + rowp)*M) + lane8*2;
        pf[it*2]   = p[0];
        pf[it*2+1] = p[1];
    }

    spin_on(&fD[b]);

    int m0 = lane8 * 8;
    float4 e0v = *(const float4*)(g_ea + b*2*M + m0);
    float4 e1v = *(const float4*)(g_ea + b*2*M + m0 + 4);
    float4 a0v = *(const float4*)(g_ea + b*2*M + M + m0);
    float4 a1v = *(const float4*)(g_ea + b*2*M + M + m0 + 4);

    #pragma unroll
    for (int it = 0; it < 4; it++) {
        float w = whead[(size_t)b*N + xt*DTILE + it*32 + rowp];
        float4 v0 = pf[it*2], v1 = pf[it*2+1];
        float4 o0, o1;
        o0.x = v0.x*(1.0f - w*e0v.x) + w*a0v.x;
        o0.y = v0.y*(1.0f - w*e0v.y) + w*a0v.y;
        o0.z = v0.z*(1.0f - w*e0v.z) + w*a0v.z;
        o0.w = v0.w*(1.0f - w*e0v.w) + w*a0v.w;
        o1.x = v1.x*(1.0f - w*e1v.x) + w*a1v.x;
        o1.y = v1.y*(1.0f - w*e1v.y) + w*a1v.y;
        o1.z = v1.z*(1.0f - w*e1v.z) + w*a1v.z;
        o1.w = v1.w*(1.0f - w*e1v.w) + w*a1v.w;
        float4* q = (float4*)(outM + base + (size_t)(it*32 + rowp)*M) + lane8*2;
        __stcs(q,     o0);
        __stcs(q + 1, o1);
    }
}

// ===========================================================================
// KA: ctrl(read) [0,64) | gemm [64,128) | addr(read) [128,192) |
//     per-batch interleave [dot x64 | mread x64] [192, 192+8192)
// ===========================================================================
__global__ void __launch_bounds__(256) kA_kernel(
    const float* __restrict__ Mem, const float* __restrict__ inp,
    const float* __restrict__ h, const float* __restrict__ rhead_prev,
    float* __restrict__ out_r,
    const float* __restrict__ W_ih, const float* __restrict__ b_ih,
    const float* __restrict__ W_hh, const float* __restrict__ b_hh,
    const float* __restrict__ kw, const float* __restrict__ kb,
    const float* __restrict__ cw, const float* __restrict__ cb,
    const float* __restrict__ sw, const float* __restrict__ sb)
{
    int bid = blockIdx.x;
    if (bid < B) {
        if (threadIdx.x == 0) {
            fC[bid] = 0; fD[bid] = 0; dcntB[bid] = 0;   // reset KB flags
            if (bid == 0) ctrC = 0;
        }
        controller_dev(bid, h, kw, kb, cw, cb, sw, sb, nullptr, nullptr);
        release(&fA[bid]);
        return;
    }
    if (bid < 2*B) {
        gemm_partial(bid - B, inp, h, W_ih, b_ih, W_hh, b_hh);
        return;
    }
    if (bid < 3*B) {
        int b = bid - 2*B;
        spin_count(&dcntA[b], 64);
        address_dev(b, rhead_prev, out_r);
        release(&fB[b]);
        return;
    }
    int idx = bid - 3*B;
    int b   = idx >> 7;
    int sub = idx & 127;
    if (sub < 64) dot_tile(Mem, b, sub, fA, dcntA);
    else          mread_chunk(Mem, out_r, b, sub - 64);
}

// ===========================================================================
// KB: fixup [0,128) | ctrl(write) [128,192) | addr(write) [192,256) |
//     per-batch interleave [dot x64 | mout x64] [256, 256+8192)
// ===========================================================================
__global__ void __launch_bounds__(256) kB_kernel(
    const float* __restrict__ Mem, const float* __restrict__ whead_prev,
    const float* __restrict__ W_ih, const float* __restrict__ c,
    float* __restrict__ out_h, float* __restrict__ out_c,
    float* __restrict__ out_w, float* __restrict__ out_m,
    const float* __restrict__ wk_w, const float* __restrict__ wk_b,
    const float* __restrict__ wc_w, const float* __restrict__ wc_b,
    const float* __restrict__ ws_w, const float* __restrict__ ws_b,
    const float* __restrict__ w_w,  const float* __restrict__ w_b)
{
    int bid = blockIdx.x;
    if (bid < 128) {
        fixup_dev(bid, W_ih, c, out_h, out_c);
        return;
    }
    if (bid < 192) {
        int b = bid - 128;
        if (threadIdx.x == 0) {
            fA[b] = 0; fB[b] = 0; dcntA[b] = 0; mcnt[b] = 0;   // reset KA flags
        }
        spin_count(&ctrC, 128);
        controller_dev(b, out_h, wk_w, wk_b, wc_w, wc_b, ws_w, ws_b, w_w, w_b);
        release(&fC[b]);
        return;
    }
    if (bid < 256) {
        int b = bid - 192;
        spin_count(&dcntB[b], 64);
        address_dev(b, whead_prev, out_w);
        release(&fD[b]);
        return;
    }
    int idx = bid - 256;
    int b   = idx >> 7;
    int sub = idx & 127;
    if (sub < 64) dot_tile(Mem, b, sub, fC, dcntB);
    else          mout_tile(Mem, out_w, out_m, b, sub - 64);
}

// ---------------------------------------------------------------------------
extern "C" void kernel_launch(void* const* d_in, const int* in_sizes, int n_in,
                              void* d_out, int out_size)
{
    const float* inp    = (const float*)d_in[0];
    const float* h      = (const float*)d_in[1];
    const float* c      = (const float*)d_in[2];
    const float* rhead  = (const float*)d_in[3];
    const float* whead  = (const float*)d_in[4];
    const float* mem    = (const float*)d_in[5];
    const float* W_ih   = (const float*)d_in[6];
    const float* b_ih   = (const float*)d_in[7];
    const float* W_hh   = (const float*)d_in[8];
    const float* b_hh   = (const float*)d_in[9];
    const float* rk_w   = (const float*)d_in[10];
    const float* rk_b   = (const float*)d_in[11];
    const float* rc_w   = (const float*)d_in[12];
    const float* rc_b   = (const float*)d_in[13];
    const float* rs_w   = (const float*)d_in[14];
    const float* rs_b   = (const float*)d_in[15];
    const float* wk_w   = (const float*)d_in[16];
    const float* wk_b   = (const float*)d_in[17];
    const float* wc_w   = (const float*)d_in[18];
    const float* wc_b   = (const float*)d_in[19];
    const float* ws_w   = (const float*)d_in[20];
    const float* ws_b   = (const float*)d_in[21];
    const float* w_w    = (const float*)d_in[22];
    const float* w_b    = (const float*)d_in[23];

    float* out   = (float*)d_out;
    float* out_h = out;
    float* out_c = out + OUT_C_OFF;
    float* out_r = out + OUT_R_OFF;
    float* out_w = out + OUT_W_OFF;
    float* out_m = out + OUT_M_OFF;

    kA_kernel<<<3*B + B*128, 256>>>(mem, inp, h, rhead, out_r,
                                    W_ih, b_ih, W_hh, b_hh,
                                    rk_w, rk_b, rc_w, rc_b, rs_w, rs_b);
    kB_kernel<<<256 + B*128, 256>>>(mem, whead, W_ih, c,
                                    out_h, out_c, out_w, out_m,
                                    wk_w, wk_b, wc_w, wc_b, ws_w, ws_b,
                                    w_w, w_b);
}

// round 7
// speedup vs baseline: 1.1414x; 1.1414x over previous
#include <cuda_runtime.h>
#include <cuda_bf16.h>
#include <float.h>
#include <math.h>

// Problem constants
#define B 64
#define IN_DIM 256
#define H 512
#define M 64
#define N 8192
#define GJ 2048          // 4*H
#define KPART 768        // inp + h K-columns
#define DTILE 128        // rows per Mem tile (64 tiles per batch)

// Output layout (floats)
#define OUT_C_OFF (B*H)
#define OUT_R_OFF (2*B*H)
#define OUT_W_OFF (2*B*H + B*N)
#define OUT_M_OFF (2*B*H + 2*B*N)

// Scratch (static device globals — no allocation)
__device__ float g_k[B*M];
__device__ __align__(128) float g_par[B*32];
__device__ float g_logit[B*N];
__device__ float g_mpart[B*64*M];
__device__ float g_Mread[B*M];
__device__ float g_gatesT[GJ*B];              // partial gates [j][b]
__device__ float g_ea[B*2*M];

// Flags/counters (zero-init; each kernel resets the OTHER kernel's)
__device__ int fA[B];       // KA ctrl  -> KA tiles(dot)    (reset by KB)
__device__ int dcntA[B];    // KA dot   -> KA address       (reset by KB)
__device__ int fB[B];       // KA addr  -> KA tiles(mread)  (reset by KB)
__device__ int mcnt[B];     // KA mread chunk counter       (reset by KB)
__device__ int ctrC;        // KB fixup -> KB controller    (reset by KA)
__device__ int fC[B];       // KB ctrl  -> KB tiles(dot)    (reset by KA)
__device__ int dcntB[B];    // KB dot   -> KB address       (reset by KA)
__device__ int fD[B];       // KB addr  -> KB tiles(mout)   (reset by KA)

__device__ __forceinline__ float sigf(float x) { return 1.0f / (1.0f + __expf(-x)); }

__device__ __forceinline__ void spin_on(int* f)
{
    if (threadIdx.x == 0) {
        while (atomicAdd(f, 0) == 0) __nanosleep(64);
    }
    __syncthreads();
    __threadfence();
}

__device__ __forceinline__ void spin_count(int* c, int target)
{
    if (threadIdx.x == 0) {
        while (atomicAdd(c, 0) < target) __nanosleep(64);
    }
    __syncthreads();
    __threadfence();
}

__device__ __forceinline__ void release(int* f)
{
    __threadfence();
    __syncthreads();
    if (threadIdx.x == 0) atomicExch(f, 1);
}

// ---------------------------------------------------------------------------
// Block reductions (256 threads, 8 warps)
// ---------------------------------------------------------------------------
__device__ __forceinline__ float bsum(float v, float* red)
{
    #pragma unroll
    for (int o = 16; o; o >>= 1) v += __shfl_xor_sync(0xffffffffu, v, o);
    int t = threadIdx.x;
    if ((t & 31) == 0) red[t >> 5] = v;
    __syncthreads();
    if (t < 8) {
        v = red[t];
        #pragma unroll
        for (int o = 4; o; o >>= 1) v += __shfl_xor_sync(0xffu, v, o);
        if (t == 0) red[0] = v;
    }
    __syncthreads();
    float r = red[0];
    __syncthreads();
    return r;
}

__device__ __forceinline__ float bmax(float v, float* red)
{
    #pragma unroll
    for (int o = 16; o; o >>= 1) v = fmaxf(v, __shfl_xor_sync(0xffffffffu, v, o));
    int t = threadIdx.x;
    if ((t & 31) == 0) red[t >> 5] = v;
    __syncthreads();
    if (t < 8) {
        v = red[t];
        #pragma unroll
        for (int o = 4; o; o >>= 1) v = fmaxf(v, __shfl_xor_sync(0xffu, v, o));
        if (t == 0) red[0] = v;
    }
    __syncthreads();
    float r = red[0];
    __syncthreads();
    return r;
}

// ---------------------------------------------------------------------------
// Controller (one block per batch, 256 threads)
// ---------------------------------------------------------------------------
__device__ void controller_dev(int b, const float* __restrict__ hstate,
                               const float* __restrict__ kw, const float* __restrict__ kb,
                               const float* __restrict__ cw, const float* __restrict__ cb,
                               const float* __restrict__ sw, const float* __restrict__ sb,
                               const float* __restrict__ ww, const float* __restrict__ wb)
{
    int t = threadIdx.x;
    __shared__ float hs[H];
    __shared__ float ks[M];
    __shared__ float cvs[3];
    __shared__ float ss[3];

    for (int i = t; i < H; i += 256) hs[i] = hstate[(size_t)b*H + i];
    __syncthreads();

    if (t < M) {
        const float4* w4 = (const float4*)(kw + (size_t)t * H);
        float acc = kb[t];
        #pragma unroll 8
        for (int q = 0; q < H/4; q++) {
            float4 wv = w4[q]; int j = q*4;
            acc += wv.x*hs[j] + wv.y*hs[j+1] + wv.z*hs[j+2] + wv.w*hs[j+3];
        }
        ks[t] = tanhf(acc);
    } else if (t < M + 3) {
        int r = t - M;
        const float4* w4 = (const float4*)(cw + (size_t)r * H);
        float acc = cb[r];
        for (int q = 0; q < H/4; q++) {
            float4 wv = w4[q]; int j = q*4;
            acc += wv.x*hs[j] + wv.y*hs[j+1] + wv.z*hs[j+2] + wv.w*hs[j+3];
        }
        cvs[r] = acc;
    } else if (t < M + 6) {
        int r = t - M - 3;
        const float4* w4 = (const float4*)(sw + (size_t)r * H);
        float acc = sb[r];
        for (int q = 0; q < H/4; q++) {
            float4 wv = w4[q]; int j = q*4;
            acc += wv.x*hs[j] + wv.y*hs[j+1] + wv.z*hs[j+2] + wv.w*hs[j+3];
        }
        ss[r] = acc;
    } else if (ww != nullptr && t >= 70 && t < 70 + 2*M) {
        int r = t - 70;
        const float4* w4 = (const float4*)(ww + (size_t)r * H);
        float acc = wb[r];
        for (int q = 0; q < H/4; q++) {
            float4 wv = w4[q]; int j = q*4;
            acc += wv.x*hs[j] + wv.y*hs[j+1] + wv.z*hs[j+2] + wv.w*hs[j+3];
        }
        g_ea[b*2*M + r] = (r < M) ? sigf(acc) : acc;
    }
    __syncthreads();

    if (t < M) g_k[b*M + t] = ks[t];
    if (t == 0) {
        float mx = fmaxf(ss[0], fmaxf(ss[1], ss[2]));
        float e0 = __expf(ss[0]-mx), e1 = __expf(ss[1]-mx), e2 = __expf(ss[2]-mx);
        float tot = e0 + e1 + e2;
        float nk = 0.0f;
        for (int j = 0; j < M; j++) nk += ks[j]*ks[j];
        g_par[b*32 + 0] = fmaxf(cvs[0], 0.0f) + 0.0001f;
        g_par[b*32 + 1] = sigf(cvs[1]);
        g_par[b*32 + 2] = fmaxf(cvs[2], 0.0f) + 1.0001f;
        g_par[b*32 + 3] = e0/tot;
        g_par[b*32 + 4] = e1/tot;
        g_par[b*32 + 5] = e2/tot;
        g_par[b*32 + 6] = nk;
    }
}

// ---------------------------------------------------------------------------
// GEMM-partial: gatesT[j][b] = bias_j + inp[b]@W_ih[j,:256] + h[b]@W_hh[j,:]
// ---------------------------------------------------------------------------
__device__ void gemm_partial(int gbid,
                             const float* __restrict__ inp,
                             const float* __restrict__ h,
                             const float* __restrict__ W_ih,
                             const float* __restrict__ b_ih,
                             const float* __restrict__ W_hh,
                             const float* __restrict__ b_hh)
{
    __shared__ float Xs[64][33];
    __shared__ float Ws[32][33];
    int t  = threadIdx.x;
    int tx = t & 15;
    int ty = t >> 4;
    int jbase = gbid * 32;
    int lrow = t >> 2;
    int lcol = (t & 3) * 8;
    int wrow = t >> 3;
    int wcol = (t & 7) * 4;

    float acc[4][2];
    #pragma unroll
    for (int i = 0; i < 4; i++) { acc[i][0] = 0.0f; acc[i][1] = 0.0f; }

    for (int kc = 0; kc < KPART/32; kc++) {
        int k0 = kc * 32;
        const float* xsrc = (k0 < IN_DIM)
            ? (inp + (size_t)lrow*IN_DIM + k0 + lcol)
            : (h   + (size_t)lrow*H + (k0 - IN_DIM) + lcol);
        float4 xa = *(const float4*)xsrc;
        float4 xb = *(const float4*)(xsrc + 4);
        Xs[lrow][lcol+0]=xa.x; Xs[lrow][lcol+1]=xa.y; Xs[lrow][lcol+2]=xa.z; Xs[lrow][lcol+3]=xa.w;
        Xs[lrow][lcol+4]=xb.x; Xs[lrow][lcol+5]=xb.y; Xs[lrow][lcol+6]=xb.z; Xs[lrow][lcol+7]=xb.w;
        const float* wsrc = (k0 < IN_DIM)
            ? (W_ih + (size_t)(jbase + wrow)*(IN_DIM + M) + k0 + wcol)
            : (W_hh + (size_t)(jbase + wrow)*H + (k0 - IN_DIM) + wcol);
        float4 wa = *(const float4*)wsrc;
        Ws[wrow][wcol+0]=wa.x; Ws[wrow][wcol+1]=wa.y; Ws[wrow][wcol+2]=wa.z; Ws[wrow][wcol+3]=wa.w;
        __syncthreads();
        #pragma unroll
        for (int k = 0; k < 32; k++) {
            float xv[4], wv[2];
            #pragma unroll
            for (int i = 0; i < 4; i++) xv[i] = Xs[tx*4 + i][k];
            wv[0] = Ws[ty*2 + 0][k];
            wv[1] = Ws[ty*2 + 1][k];
            #pragma unroll
            for (int i = 0; i < 4; i++) {
                acc[i][0] += xv[i] * wv[0];
                acc[i][1] += xv[i] * wv[1];
            }
        }
        __syncthreads();
    }
    #pragma unroll
    for (int jj = 0; jj < 2; jj++) {
        int j = jbase + ty*2 + jj;
        float bias = b_ih[j] + b_hh[j];
        #pragma unroll
        for (int i = 0; i < 4; i++)
            g_gatesT[(size_t)j*B + (tx*4 + i)] = acc[i][jj] + bias;
    }
}

// ---------------------------------------------------------------------------
// Address (256 threads)
// ---------------------------------------------------------------------------
__device__ void address_dev(int b, const float* __restrict__ head_prev,
                            float* __restrict__ out_head)
{
    __shared__ float A[N];       // 32KB
    __shared__ float red[8];
    int t = threadIdx.x;
    float g     = g_par[b*32 + 1];
    float gamma = g_par[b*32 + 2];
    float s0    = g_par[b*32 + 3];
    float s1    = g_par[b*32 + 4];
    float s2    = g_par[b*32 + 5];

    const float* lg = g_logit + (size_t)b*N;
    float vmax = -FLT_MAX;
    #pragma unroll
    for (int i = 0; i < 32; i++) {
        float v = lg[i*256 + t];
        A[i*256 + t] = v;
        vmax = fmaxf(vmax, v);
    }
    vmax = bmax(vmax, red);

    float lsum = 0.0f;
    #pragma unroll
    for (int i = 0; i < 32; i++) {
        int idx = i*256 + t;
        float e = __expf(A[idx] - vmax);
        A[idx] = e;
        lsum += e;
    }
    float inv = 1.0f / bsum(lsum, red);

    const float* hp = head_prev + (size_t)b*N;
    #pragma unroll
    for (int i = 0; i < 32; i++) {
        int idx = i*256 + t;
        A[idx] = g * (A[idx] * inv) + (1.0f - g) * hp[idx];
    }
    __syncthreads();

    float p[32];
    float psum = 0.0f;
    #pragma unroll
    for (int i = 0; i < 32; i++) {
        int idx = i*256 + t;
        float o = s0 * A[(idx + N - 2) & (N-1)]
                + s1 * A[(idx + N - 1) & (N-1)]
                + s2 * A[idx];
        p[i] = __powf(o, gamma);
        psum += p[i];
    }
    float inv2 = 1.0f / bsum(psum, red);
    #pragma unroll
    for (int i = 0; i < 32; i++)
        out_head[(size_t)b*N + i*256 + t] = p[i] * inv2;
}

// ---------------------------------------------------------------------------
// KA fused tile: ONE Mem read serves dot AND mread.
// prefetch -> spin(ctrl) -> dot -> bump dcntA -> spin(addr) -> mread partial.
// ---------------------------------------------------------------------------
__device__ void tileA(const float* __restrict__ Mem,
                      const float* __restrict__ out_r, int tile)
{
    int b  = tile >> 6;
    int xt = tile & 63;
    int t = threadIdx.x;
    int lane8 = t & 7, rowp = t >> 3;

    float4 pf[8];
    size_t base = ((size_t)b*N + xt*DTILE)*M;
    #pragma unroll
    for (int it = 0; it < 4; it++) {
        const float4* p = (const float4*)(Mem + base + (size_t)(it*32 + rowp)*M) + lane8*2;
        pf[it*2]   = p[0];
        pf[it*2+1] = p[1];
    }

    spin_on(&fA[b]);

    // ---- dot ----
    {
        int m0 = lane8 * 8;
        float4 ka = *(const float4*)(g_k + b*M + m0);
        float4 kb4 = *(const float4*)(g_k + b*M + m0 + 4);
        float beta = g_par[b*32 + 0];
        float nk   = g_par[b*32 + 6];
        #pragma unroll
        for (int it = 0; it < 4; it++) {
            float4 v0 = pf[it*2], v1 = pf[it*2+1];
            float d  = v0.x*ka.x + v0.y*ka.y + v0.z*ka.z + v0.w*ka.w
                     + v1.x*kb4.x + v1.y*kb4.y + v1.z*kb4.z + v1.w*kb4.w;
            float nm = v0.x*v0.x + v0.y*v0.y + v0.z*v0.z + v0.w*v0.w
                     + v1.x*v1.x + v1.y*v1.y + v1.z*v1.z + v1.w*v1.w;
            #pragma unroll
            for (int o = 4; o; o >>= 1) {
                d  += __shfl_xor_sync(0xffffffffu, d,  o);
                nm += __shfl_xor_sync(0xffffffffu, nm, o);
            }
            if (lane8 == 0) g_logit[(size_t)b*N + xt*DTILE + it*32 + rowp] = beta * d / (nm * nk);
        }
    }
    __threadfence();
    __syncthreads();
    if (t == 0) atomicAdd(&dcntA[b], 1);

    // ---- wait for address, then mread using the SAME registers ----
    spin_on(&fB[b]);

    float a0=0,a1=0,a2=0,a3=0,a4=0,a5=0,a6=0,a7=0;
    const float* hp = out_r + (size_t)b*N + xt*DTILE;
    #pragma unroll
    for (int it = 0; it < 4; it++) {
        float r = hp[it*32 + rowp];
        float4 v0 = pf[it*2], v1 = pf[it*2+1];
        a0 += r*v0.x; a1 += r*v0.y; a2 += r*v0.z; a3 += r*v0.w;
        a4 += r*v1.x; a5 += r*v1.y; a6 += r*v1.z; a7 += r*v1.w;
    }

    __shared__ float sdata[256*8];
    float* s = sdata + t*8;
    s[0]=a0; s[1]=a1; s[2]=a2; s[3]=a3; s[4]=a4; s[5]=a5; s[6]=a6; s[7]=a7;
    __syncthreads();
    if (t < 64) {
        int lg2 = t >> 3, j = t & 7;
        float acc = 0.0f;
        #pragma unroll
        for (int rw = 0; rw < 32; rw++) acc += sdata[((rw<<3) | lg2)*8 + j];
        g_mpart[((size_t)b*64 + xt)*M + lg2*8 + j] = acc;
    }

    __threadfence();
    __syncthreads();
    __shared__ int lastf;
    if (t == 0) lastf = (atomicAdd(&mcnt[b], 1) == 63) ? 1 : 0;
    __syncthreads();
    if (lastf) {
        __threadfence();
        int k = t & 63, q = t >> 6;
        float a = 0.0f;
        #pragma unroll
        for (int p = 0; p < 16; p++)
            a += g_mpart[((size_t)b*64 + q*16 + p)*M + k];
        __shared__ float sr[256];
        sr[t] = a;
        __syncthreads();
        if (t < 64) g_Mread[b*M + t] = sr[t] + sr[64+t] + sr[128+t] + sr[192+t];
    }
}

// ---------------------------------------------------------------------------
// KB fused tile: ONE Mem read serves dot(write) AND mout.
// prefetch -> spin(ctrl) -> dot -> bump dcntB -> spin(addr) -> mout store.
// ---------------------------------------------------------------------------
__device__ void tileB(const float* __restrict__ Mem,
                      const float* __restrict__ out_w,
                      float* __restrict__ outM, int tile_rev)
{
    int b  = B - 1 - (tile_rev >> 6);       // reversed (serpentine vs KA)
    int xt = 63 - (tile_rev & 63);
    int t = threadIdx.x;
    int lane8 = t & 7, rowp = t >> 3;

    float4 pf[8];
    size_t base = ((size_t)b*N + xt*DTILE)*M;
    #pragma unroll
    for (int it = 0; it < 4; it++) {
        const float4* p = (const float4*)(Mem + base + (size_t)(it*32 + rowp)*M) + lane8*2;
        pf[it*2]   = p[0];
        pf[it*2+1] = p[1];
    }

    spin_on(&fC[b]);

    // ---- dot(write) ----
    {
        int m0 = lane8 * 8;
        float4 ka = *(const float4*)(g_k + b*M + m0);
        float4 kb4 = *(const float4*)(g_k + b*M + m0 + 4);
        float beta = g_par[b*32 + 0];
        float nk   = g_par[b*32 + 6];
        #pragma unroll
        for (int it = 0; it < 4; it++) {
            float4 v0 = pf[it*2], v1 = pf[it*2+1];
            float d  = v0.x*ka.x + v0.y*ka.y + v0.z*ka.z + v0.w*ka.w
                     + v1.x*kb4.x + v1.y*kb4.y + v1.z*kb4.z + v1.w*kb4.w;
            float nm = v0.x*v0.x + v0.y*v0.y + v0.z*v0.z + v0.w*v0.w
                     + v1.x*v1.x + v1.y*v1.y + v1.z*v1.z + v1.w*v1.w;
            #pragma unroll
            for (int o = 4; o; o >>= 1) {
                d  += __shfl_xor_sync(0xffffffffu, d,  o);
                nm += __shfl_xor_sync(0xffffffffu, nm, o);
            }
            if (lane8 == 0) g_logit[(size_t)b*N + xt*DTILE + it*32 + rowp] = beta * d / (nm * nk);
        }
    }
    __threadfence();
    __syncthreads();
    if (t == 0) atomicAdd(&dcntB[b], 1);

    // ---- wait for address, then mout using the SAME registers ----
    spin_on(&fD[b]);

    int m0 = lane8 * 8;
    float4 e0v = *(const float4*)(g_ea + b*2*M + m0);
    float4 e1v = *(const float4*)(g_ea + b*2*M + m0 + 4);
    float4 a0v = *(const float4*)(g_ea + b*2*M + M + m0);
    float4 a1v = *(const float4*)(g_ea + b*2*M + M + m0 + 4);

    #pragma unroll
    for (int it = 0; it < 4; it++) {
        float w = out_w[(size_t)b*N + xt*DTILE + it*32 + rowp];
        float4 v0 = pf[it*2], v1 = pf[it*2+1];
        float4 o0, o1;
        o0.x = v0.x*(1.0f - w*e0v.x) + w*a0v.x;
        o0.y = v0.y*(1.0f - w*e0v.y) + w*a0v.y;
        o0.z = v0.z*(1.0f - w*e0v.z) + w*a0v.z;
        o0.w = v0.w*(1.0f - w*e0v.w) + w*a0v.w;
        o1.x = v1.x*(1.0f - w*e1v.x) + w*a1v.x;
        o1.y = v1.y*(1.0f - w*e1v.y) + w*a1v.y;
        o1.z = v1.z*(1.0f - w*e1v.z) + w*a1v.z;
        o1.w = v1.w*(1.0f - w*e1v.w) + w*a1v.w;
        float4* q = (float4*)(outM + base + (size_t)(it*32 + rowp)*M) + lane8*2;
        __stcs(q,     o0);
        __stcs(q + 1, o1);
    }
}

// ---------------------------------------------------------------------------
// Fixup + LSTM: gates = gatesT + M_read @ W_mid; h_new/c_new (4 h per block)
// ---------------------------------------------------------------------------
__device__ void fixup_dev(int blk, const float* __restrict__ W_ih,
                          const float* __restrict__ c,
                          float* __restrict__ out_h, float* __restrict__ out_c)
{
    __shared__ float Wm[16][65];
    __shared__ float Mr[64][65];
    int t = threadIdx.x;
    int hbase = blk * 4;

    {
        int r = t >> 4;
        int off = (t & 15) * 4;
        int gate = r >> 2, hloc = r & 3;
        float4 v = *(const float4*)(W_ih + (size_t)(gate*H + hbase + hloc)*(IN_DIM + M) + IN_DIM + off);
        Wm[r][off+0]=v.x; Wm[r][off+1]=v.y; Wm[r][off+2]=v.z; Wm[r][off+3]=v.w;
    }
    {
        int row = t >> 2;
        int col = (t & 3) * 16;
        const float4* src = (const float4*)(g_Mread + (size_t)row*M + col);
        float4 v0 = src[0], v1 = src[1], v2 = src[2], v3 = src[3];
        Mr[row][col+ 0]=v0.x; Mr[row][col+ 1]=v0.y; Mr[row][col+ 2]=v0.z; Mr[row][col+ 3]=v0.w;
        Mr[row][col+ 4]=v1.x; Mr[row][col+ 5]=v1.y; Mr[row][col+ 6]=v1.z; Mr[row][col+ 7]=v1.w;
        Mr[row][col+ 8]=v2.x; Mr[row][col+ 9]=v2.y; Mr[row][col+10]=v2.z; Mr[row][col+11]=v2.w;
        Mr[row][col+12]=v3.x; Mr[row][col+13]=v3.y; Mr[row][col+14]=v3.z; Mr[row][col+15]=v3.w;
    }
    __syncthreads();

    int b = t & 63;
    int hloc = t >> 6;
    int hh = hbase + hloc;

    float acc[4];
    #pragma unroll
    for (int g4 = 0; g4 < 4; g4++)
        acc[g4] = g_gatesT[(size_t)(g4*H + hh)*B + b];
    #pragma unroll 8
    for (int k = 0; k < M; k++) {
        float m = Mr[b][k];
        #pragma unroll
        for (int g4 = 0; g4 < 4; g4++) acc[g4] += m * Wm[g4*4 + hloc][k];
    }

    float cn = sigf(acc[1]) * c[(size_t)b*H + hh] + sigf(acc[0]) * tanhf(acc[2]);
    float hn = sigf(acc[3]) * tanhf(cn);
    out_c[(size_t)b*H + hh] = cn;
    out_h[(size_t)b*H + hh] = hn;

    __threadfence();
    __syncthreads();
    if (t == 0) atomicAdd(&ctrC, 1);
}

// ===========================================================================
// KA: ctrl(read) [0,64) | gemm [64,128) | addr(read) [128,192) |
//     fused dot+mread tiles [192, 192+4096)
// ===========================================================================
__global__ void __launch_bounds__(256) kA_kernel(
    const float* __restrict__ Mem, const float* __restrict__ inp,
    const float* __restrict__ h, const float* __restrict__ rhead_prev,
    float* __restrict__ out_r,
    const float* __restrict__ W_ih, const float* __restrict__ b_ih,
    const float* __restrict__ W_hh, const float* __restrict__ b_hh,
    const float* __restrict__ kw, const float* __restrict__ kb,
    const float* __restrict__ cw, const float* __restrict__ cb,
    const float* __restrict__ sw, const float* __restrict__ sb)
{
    int bid = blockIdx.x;
    if (bid < B) {
        if (threadIdx.x == 0) {
            fC[bid] = 0; fD[bid] = 0; dcntB[bid] = 0;   // reset KB flags
            if (bid == 0) ctrC = 0;
        }
        controller_dev(bid, h, kw, kb, cw, cb, sw, sb, nullptr, nullptr);
        release(&fA[bid]);
        return;
    }
    if (bid < 2*B) {
        gemm_partial(bid - B, inp, h, W_ih, b_ih, W_hh, b_hh);
        return;
    }
    if (bid < 3*B) {
        int b = bid - 2*B;
        spin_count(&dcntA[b], 64);
        address_dev(b, rhead_prev, out_r);
        release(&fB[b]);
        return;
    }
    tileA(Mem, out_r, bid - 3*B);
}

// ===========================================================================
// KB: fixup [0,128) | ctrl(write) [128,192) | addr(write) [192,256) |
//     fused dot+mout tiles [256, 256+4096)   (reversed serpentine)
// ===========================================================================
__global__ void __launch_bounds__(256) kB_kernel(
    const float* __restrict__ Mem, const float* __restrict__ whead_prev,
    const float* __restrict__ W_ih, const float* __restrict__ c,
    float* __restrict__ out_h, float* __restrict__ out_c,
    float* __restrict__ out_w, float* __restrict__ out_m,
    const float* __restrict__ wk_w, const float* __restrict__ wk_b,
    const float* __restrict__ wc_w, const float* __restrict__ wc_b,
    const float* __restrict__ ws_w, const float* __restrict__ ws_b,
    const float* __restrict__ w_w,  const float* __restrict__ w_b)
{
    int bid = blockIdx.x;
    if (bid < 128) {
        fixup_dev(bid, W_ih, c, out_h, out_c);
        return;
    }
    if (bid < 192) {
        int b = bid - 128;
        if (threadIdx.x == 0) {
            fA[b] = 0; fB[b] = 0; dcntA[b] = 0; mcnt[b] = 0;   // reset KA flags
        }
        spin_count(&ctrC, 128);
        controller_dev(b, out_h, wk_w, wk_b, wc_w, wc_b, ws_w, ws_b, w_w, w_b);
        release(&fC[b]);
        return;
    }
    if (bid < 256) {
        int b = bid - 192;
        spin_count(&dcntB[b], 64);
        address_dev(b, whead_prev, out_w);
        release(&fD[b]);
        return;
    }
    tileB(Mem, out_w, out_m, bid - 256);
}

// ---------------------------------------------------------------------------
extern "C" void kernel_launch(void* const* d_in, const int* in_sizes, int n_in,
                              void* d_out, int out_size)
{
    const float* inp    = (const float*)d_in[0];
    const float* h      = (const float*)d_in[1];
    const float* c      = (const float*)d_in[2];
    const float* rhead  = (const float*)d_in[3];
    const float* whead  = (const float*)d_in[4];
    const float* mem    = (const float*)d_in[5];
    const float* W_ih   = (const float*)d_in[6];
    const float* b_ih   = (const float*)d_in[7];
    const float* W_hh   = (const float*)d_in[8];
    const float* b_hh   = (const float*)d_in[9];
    const float* rk_w   = (const float*)d_in[10];
    const float* rk_b   = (const float*)d_in[11];
    const float* rc_w   = (const float*)d_in[12];
    const float* rc_b   = (const float*)d_in[13];
    const float* rs_w   = (const float*)d_in[14];
    const float* rs_b   = (const float*)d_in[15];
    const float* wk_w   = (const float*)d_in[16];
    const float* wk_b   = (const float*)d_in[17];
    const float* wc_w   = (const float*)d_in[18];
    const float* wc_b   = (const float*)d_in[19];
    const float* ws_w   = (const float*)d_in[20];
    const float* ws_b   = (const float*)d_in[21];
    const float* w_w    = (const float*)d_in[22];
    const float* w_b    = (const float*)d_in[23];

    float* out   = (float*)d_out;
    float* out_h = out;
    float* out_c = out + OUT_C_OFF;
    float* out_r = out + OUT_R_OFF;
    float* out_w = out + OUT_W_OFF;
    float* out_m = out + OUT_M_OFF;

    kA_kernel<<<3*B + B*64, 256>>>(mem, inp, h, rhead, out_r,
                                   W_ih, b_ih, W_hh, b_hh,
                                   rk_w, rk_b, rc_w, rc_b, rs_w, rs_b);
    kB_kernel<<<256 + B*64, 256>>>(mem, whead, W_ih, c,
                                   out_h, out_c, out_w, out_m,
                                   wk_w, wk_b, wc_w, wc_b, ws_w, ws_b,
                                   w_w, w_b);
}

// round 8
// speedup vs baseline: 1.6366x; 1.4339x over previous
#include <cuda_runtime.h>
#include <cuda_bf16.h>
#include <float.h>
#include <math.h>

// Problem constants
#define B 64
#define IN_DIM 256
#define H 512
#define M 64
#define N 8192
#define GJ 2048          // 4*H
#define KPART 768        // inp + h K-columns
#define DTILE 128        // rows per Mem tile (64 tiles per batch)
#define HB 32            // half-batch group size

// Output layout (floats)
#define OUT_C_OFF (B*H)
#define OUT_R_OFF (2*B*H)
#define OUT_W_OFF (2*B*H + B*N)
#define OUT_M_OFF (2*B*H + 2*B*N)

// Scratch (static device globals — no allocation)
__device__ float g_k[B*M];
__device__ __align__(128) float g_par[B*32];
__device__ float g_logit[B*N];
__device__ float g_mpart[B*64*M];
__device__ float g_Mread[B*M];
__device__ float g_gatesT[GJ*B];              // partial gates [j][b]
__device__ float g_ea[B*2*M];

// Flags (zero-init). Reset schedule (all after last use, before next set):
//  fA   set K1, used K1          -> reset in K2 addr blocks
//  fB   set K2/K3, used K2/K3    -> reset in K4 fixup blocks
//  mcnt set K2/K3, used K2/K3    -> reset in K4 fixup blocks
//  ctrC set K4, used K4          -> reset in K6 addr block 0
//  fC   set K4, used K4          -> reset in K5 addr blocks
//  fD   set K5/K6, used K5/K6    -> reset in K1 ctrl blocks
__device__ int fA[B];
__device__ int fB[B];
__device__ int mcnt[B];
__device__ int ctrC;
__device__ int fC[B];
__device__ int fD[B];

__device__ __forceinline__ float sigf(float x) { return 1.0f / (1.0f + __expf(-x)); }

__device__ __forceinline__ void spin_on(int* f)
{
    if (threadIdx.x == 0) {
        while (atomicAdd(f, 0) == 0) __nanosleep(64);
    }
    __syncthreads();
    __threadfence();
}

__device__ __forceinline__ void spin_count(int* c, int target)
{
    if (threadIdx.x == 0) {
        while (atomicAdd(c, 0) < target) __nanosleep(64);
    }
    __syncthreads();
    __threadfence();
}

__device__ __forceinline__ void release(int* f)
{
    __threadfence();
    __syncthreads();
    if (threadIdx.x == 0) atomicExch(f, 1);
}

// ---------------------------------------------------------------------------
// Block reductions (256 threads, 8 warps)
// ---------------------------------------------------------------------------
__device__ __forceinline__ float bsum(float v, float* red)
{
    #pragma unroll
    for (int o = 16; o; o >>= 1) v += __shfl_xor_sync(0xffffffffu, v, o);
    int t = threadIdx.x;
    if ((t & 31) == 0) red[t >> 5] = v;
    __syncthreads();
    if (t < 8) {
        v = red[t];
        #pragma unroll
        for (int o = 4; o; o >>= 1) v += __shfl_xor_sync(0xffu, v, o);
        if (t == 0) red[0] = v;
    }
    __syncthreads();
    float r = red[0];
    __syncthreads();
    return r;
}

__device__ __forceinline__ float bmax(float v, float* red)
{
    #pragma unroll
    for (int o = 16; o; o >>= 1) v = fmaxf(v, __shfl_xor_sync(0xffffffffu, v, o));
    int t = threadIdx.x;
    if ((t & 31) == 0) red[t >> 5] = v;
    __syncthreads();
    if (t < 8) {
        v = red[t];
        #pragma unroll
        for (int o = 4; o; o >>= 1) v = fmaxf(v, __shfl_xor_sync(0xffu, v, o));
        if (t == 0) red[0] = v;
    }
    __syncthreads();
    float r = red[0];
    __syncthreads();
    return r;
}

// ---------------------------------------------------------------------------
// Controller (one block per batch, 256 threads)
// ---------------------------------------------------------------------------
__device__ void controller_dev(int b, const float* __restrict__ hstate,
                               const float* __restrict__ kw, const float* __restrict__ kb,
                               const float* __restrict__ cw, const float* __restrict__ cb,
                               const float* __restrict__ sw, const float* __restrict__ sb,
                               const float* __restrict__ ww, const float* __restrict__ wb)
{
    int t = threadIdx.x;
    __shared__ float hs[H];
    __shared__ float ks[M];
    __shared__ float cvs[3];
    __shared__ float ss[3];

    for (int i = t; i < H; i += 256) hs[i] = hstate[(size_t)b*H + i];
    __syncthreads();

    if (t < M) {
        const float4* w4 = (const float4*)(kw + (size_t)t * H);
        float acc = kb[t];
        #pragma unroll 8
        for (int q = 0; q < H/4; q++) {
            float4 wv = w4[q]; int j = q*4;
            acc += wv.x*hs[j] + wv.y*hs[j+1] + wv.z*hs[j+2] + wv.w*hs[j+3];
        }
        ks[t] = tanhf(acc);
    } else if (t < M + 3) {
        int r = t - M;
        const float4* w4 = (const float4*)(cw + (size_t)r * H);
        float acc = cb[r];
        for (int q = 0; q < H/4; q++) {
            float4 wv = w4[q]; int j = q*4;
            acc += wv.x*hs[j] + wv.y*hs[j+1] + wv.z*hs[j+2] + wv.w*hs[j+3];
        }
        cvs[r] = acc;
    } else if (t < M + 6) {
        int r = t - M - 3;
        const float4* w4 = (const float4*)(sw + (size_t)r * H);
        float acc = sb[r];
        for (int q = 0; q < H/4; q++) {
            float4 wv = w4[q]; int j = q*4;
            acc += wv.x*hs[j] + wv.y*hs[j+1] + wv.z*hs[j+2] + wv.w*hs[j+3];
        }
        ss[r] = acc;
    } else if (ww != nullptr && t >= 70 && t < 70 + 2*M) {
        int r = t - 70;
        const float4* w4 = (const float4*)(ww + (size_t)r * H);
        float acc = wb[r];
        for (int q = 0; q < H/4; q++) {
            float4 wv = w4[q]; int j = q*4;
            acc += wv.x*hs[j] + wv.y*hs[j+1] + wv.z*hs[j+2] + wv.w*hs[j+3];
        }
        g_ea[b*2*M + r] = (r < M) ? sigf(acc) : acc;
    }
    __syncthreads();

    if (t < M) g_k[b*M + t] = ks[t];
    if (t == 0) {
        float mx = fmaxf(ss[0], fmaxf(ss[1], ss[2]));
        float e0 = __expf(ss[0]-mx), e1 = __expf(ss[1]-mx), e2 = __expf(ss[2]-mx);
        float tot = e0 + e1 + e2;
        float nk = 0.0f;
        for (int j = 0; j < M; j++) nk += ks[j]*ks[j];
        g_par[b*32 + 0] = fmaxf(cvs[0], 0.0f) + 0.0001f;
        g_par[b*32 + 1] = sigf(cvs[1]);
        g_par[b*32 + 2] = fmaxf(cvs[2], 0.0f) + 1.0001f;
        g_par[b*32 + 3] = e0/tot;
        g_par[b*32 + 4] = e1/tot;
        g_par[b*32 + 5] = e2/tot;
        g_par[b*32 + 6] = nk;
    }
}

// ---------------------------------------------------------------------------
// GEMM-partial: gatesT[j][b] = bias_j + inp[b]@W_ih[j,:256] + h[b]@W_hh[j,:]
// ---------------------------------------------------------------------------
__device__ void gemm_partial(int gbid,
                             const float* __restrict__ inp,
                             const float* __restrict__ h,
                             const float* __restrict__ W_ih,
                             const float* __restrict__ b_ih,
                             const float* __restrict__ W_hh,
                             const float* __restrict__ b_hh)
{
    __shared__ float Xs[64][33];
    __shared__ float Ws[32][33];
    int t  = threadIdx.x;
    int tx = t & 15;
    int ty = t >> 4;
    int jbase = gbid * 32;
    int lrow = t >> 2;
    int lcol = (t & 3) * 8;
    int wrow = t >> 3;
    int wcol = (t & 7) * 4;

    float acc[4][2];
    #pragma unroll
    for (int i = 0; i < 4; i++) { acc[i][0] = 0.0f; acc[i][1] = 0.0f; }

    for (int kc = 0; kc < KPART/32; kc++) {
        int k0 = kc * 32;
        const float* xsrc = (k0 < IN_DIM)
            ? (inp + (size_t)lrow*IN_DIM + k0 + lcol)
            : (h   + (size_t)lrow*H + (k0 - IN_DIM) + lcol);
        float4 xa = *(const float4*)xsrc;
        float4 xb = *(const float4*)(xsrc + 4);
        Xs[lrow][lcol+0]=xa.x; Xs[lrow][lcol+1]=xa.y; Xs[lrow][lcol+2]=xa.z; Xs[lrow][lcol+3]=xa.w;
        Xs[lrow][lcol+4]=xb.x; Xs[lrow][lcol+5]=xb.y; Xs[lrow][lcol+6]=xb.z; Xs[lrow][lcol+7]=xb.w;
        const float* wsrc = (k0 < IN_DIM)
            ? (W_ih + (size_t)(jbase + wrow)*(IN_DIM + M) + k0 + wcol)
            : (W_hh + (size_t)(jbase + wrow)*H + (k0 - IN_DIM) + wcol);
        float4 wa = *(const float4*)wsrc;
        Ws[wrow][wcol+0]=wa.x; Ws[wrow][wcol+1]=wa.y; Ws[wrow][wcol+2]=wa.z; Ws[wrow][wcol+3]=wa.w;
        __syncthreads();
        #pragma unroll
        for (int k = 0; k < 32; k++) {
            float xv[4], wv[2];
            #pragma unroll
            for (int i = 0; i < 4; i++) xv[i] = Xs[tx*4 + i][k];
            wv[0] = Ws[ty*2 + 0][k];
            wv[1] = Ws[ty*2 + 1][k];
            #pragma unroll
            for (int i = 0; i < 4; i++) {
                acc[i][0] += xv[i] * wv[0];
                acc[i][1] += xv[i] * wv[1];
            }
        }
        __syncthreads();
    }
    #pragma unroll
    for (int jj = 0; jj < 2; jj++) {
        int j = jbase + ty*2 + jj;
        float bias = b_ih[j] + b_hh[j];
        #pragma unroll
        for (int i = 0; i < 4; i++)
            g_gatesT[(size_t)j*B + (tx*4 + i)] = acc[i][jj] + bias;
    }
}

// ---------------------------------------------------------------------------
// Dot tile (128 rows): prefetch -> optional spin -> compute logits.
// ---------------------------------------------------------------------------
__device__ void dot_tile(const float* __restrict__ Mem, int b, int xt, int* flags)
{
    int t = threadIdx.x;
    int lane8 = t & 7, rowp = t >> 3;

    float4 pf[8];
    size_t base = ((size_t)b*N + xt*DTILE)*M;
    #pragma unroll
    for (int it = 0; it < 4; it++) {
        const float4* p = (const float4*)(Mem + base + (size_t)(it*32 + rowp)*M) + lane8*2;
        pf[it*2]   = p[0];
        pf[it*2+1] = p[1];
    }

    if (flags) spin_on(&flags[b]);

    int m0 = lane8 * 8;
    float4 ka = *(const float4*)(g_k + b*M + m0);
    float4 kb4 = *(const float4*)(g_k + b*M + m0 + 4);
    float beta = g_par[b*32 + 0];
    float nk   = g_par[b*32 + 6];

    #pragma unroll
    for (int it = 0; it < 4; it++) {
        float4 v0 = pf[it*2], v1 = pf[it*2+1];
        float d  = v0.x*ka.x + v0.y*ka.y + v0.z*ka.z + v0.w*ka.w
                 + v1.x*kb4.x + v1.y*kb4.y + v1.z*kb4.z + v1.w*kb4.w;
        float nm = v0.x*v0.x + v0.y*v0.y + v0.z*v0.z + v0.w*v0.w
                 + v1.x*v1.x + v1.y*v1.y + v1.z*v1.z + v1.w*v1.w;
        #pragma unroll
        for (int o = 4; o; o >>= 1) {
            d  += __shfl_xor_sync(0xffffffffu, d,  o);
            nm += __shfl_xor_sync(0xffffffffu, nm, o);
        }
        if (lane8 == 0) g_logit[(size_t)b*N + xt*DTILE + it*32 + rowp] = beta * d / (nm * nk);
    }
}

// ---------------------------------------------------------------------------
// Address (256 threads)
// ---------------------------------------------------------------------------
__device__ void address_dev(int b, const float* __restrict__ head_prev,
                            float* __restrict__ out_head)
{
    __shared__ float A[N];       // 32KB
    __shared__ float red[8];
    int t = threadIdx.x;
    float g     = g_par[b*32 + 1];
    float gamma = g_par[b*32 + 2];
    float s0    = g_par[b*32 + 3];
    float s1    = g_par[b*32 + 4];
    float s2    = g_par[b*32 + 5];

    const float* lg = g_logit + (size_t)b*N;
    float vmax = -FLT_MAX;
    #pragma unroll
    for (int i = 0; i < 32; i++) {
        float v = lg[i*256 + t];
        A[i*256 + t] = v;
        vmax = fmaxf(vmax, v);
    }
    vmax = bmax(vmax, red);

    float lsum = 0.0f;
    #pragma unroll
    for (int i = 0; i < 32; i++) {
        int idx = i*256 + t;
        float e = __expf(A[idx] - vmax);
        A[idx] = e;
        lsum += e;
    }
    float inv = 1.0f / bsum(lsum, red);

    const float* hp = head_prev + (size_t)b*N;
    #pragma unroll
    for (int i = 0; i < 32; i++) {
        int idx = i*256 + t;
        A[idx] = g * (A[idx] * inv) + (1.0f - g) * hp[idx];
    }
    __syncthreads();

    float p[32];
    float psum = 0.0f;
    #pragma unroll
    for (int i = 0; i < 32; i++) {
        int idx = i*256 + t;
        float o = s0 * A[(idx + N - 2) & (N-1)]
                + s1 * A[(idx + N - 1) & (N-1)]
                + s2 * A[idx];
        p[i] = __powf(o, gamma);
        psum += p[i];
    }
    float inv2 = 1.0f / bsum(psum, red);
    #pragma unroll
    for (int i = 0; i < 32; i++)
        out_head[(size_t)b*N + i*256 + t] = p[i] * inv2;
}

// ---------------------------------------------------------------------------
// M_read tile (128 rows): prefetch -> spin fB -> weighted sum -> partials;
// last tile per batch reduces to g_Mread[b].
// ---------------------------------------------------------------------------
__device__ void mread_tile(const float* __restrict__ Mem,
                           const float* __restrict__ rhead, int b, int xt)
{
    int t = threadIdx.x;
    int lane8 = t & 7, rowp = t >> 3;

    float4 pf[8];
    size_t base = ((size_t)b*N + xt*DTILE)*M;
    #pragma unroll
    for (int it = 0; it < 4; it++) {
        const float4* p = (const float4*)(Mem + base + (size_t)(it*32 + rowp)*M) + lane8*2;
        pf[it*2]   = p[0];
        pf[it*2+1] = p[1];
    }

    spin_on(&fB[b]);

    float a0=0,a1=0,a2=0,a3=0,a4=0,a5=0,a6=0,a7=0;
    const float* hp = rhead + (size_t)b*N + xt*DTILE;
    #pragma unroll
    for (int it = 0; it < 4; it++) {
        float r = hp[it*32 + rowp];
        float4 v0 = pf[it*2], v1 = pf[it*2+1];
        a0 += r*v0.x; a1 += r*v0.y; a2 += r*v0.z; a3 += r*v0.w;
        a4 += r*v1.x; a5 += r*v1.y; a6 += r*v1.z; a7 += r*v1.w;
    }

    __shared__ float sdata[256*8];
    float* s = sdata + t*8;
    s[0]=a0; s[1]=a1; s[2]=a2; s[3]=a3; s[4]=a4; s[5]=a5; s[6]=a6; s[7]=a7;
    __syncthreads();
    if (t < 64) {
        int lg2 = t >> 3, j = t & 7;
        float acc = 0.0f;
        #pragma unroll
        for (int rw = 0; rw < 32; rw++) acc += sdata[((rw<<3) | lg2)*8 + j];
        g_mpart[((size_t)b*64 + xt)*M + lg2*8 + j] = acc;
    }

    __threadfence();
    __syncthreads();
    __shared__ int lastf;
    if (t == 0) lastf = (atomicAdd(&mcnt[b], 1) == 63) ? 1 : 0;
    __syncthreads();
    if (lastf) {
        __threadfence();
        int k = t & 63, q = t >> 6;
        float a = 0.0f;
        #pragma unroll
        for (int p = 0; p < 16; p++)
            a += g_mpart[((size_t)b*64 + q*16 + p)*M + k];
        __shared__ float sr[256];
        sr[t] = a;
        __syncthreads();
        if (t < 64) g_Mread[b*M + t] = sr[t] + sr[64+t] + sr[128+t] + sr[192+t];
    }
}

// ---------------------------------------------------------------------------
// M_out tile (128 rows): prefetch -> spin fD -> update (streaming stores)
// ---------------------------------------------------------------------------
__device__ void mout_tile(const float* __restrict__ Mem,
                          const float* __restrict__ whead,
                          float* __restrict__ outM, int b, int xt)
{
    int t = threadIdx.x;
    int lane8 = t & 7, rowp = t >> 3;

    float4 pf[8];
    size_t base = ((size_t)b*N + xt*DTILE)*M;
    #pragma unroll
    for (int it = 0; it < 4; it++) {
        const float4* p = (const float4*)(Mem + base + (size_t)(it*32 + rowp)*M) + lane8*2;
        pf[it*2]   = p[0];
        pf[it*2+1] = p[1];
    }

    spin_on(&fD[b]);

    int m0 = lane8 * 8;
    float4 e0v = *(const float4*)(g_ea + b*2*M + m0);
    float4 e1v = *(const float4*)(g_ea + b*2*M + m0 + 4);
    float4 a0v = *(const float4*)(g_ea + b*2*M + M + m0);
    float4 a1v = *(const float4*)(g_ea + b*2*M + M + m0 + 4);

    #pragma unroll
    for (int it = 0; it < 4; it++) {
        float w = whead[(size_t)b*N + xt*DTILE + it*32 + rowp];
        float4 v0 = pf[it*2], v1 = pf[it*2+1];
        float4 o0, o1;
        o0.x = v0.x*(1.0f - w*e0v.x) + w*a0v.x;
        o0.y = v0.y*(1.0f - w*e0v.y) + w*a0v.y;
        o0.z = v0.z*(1.0f - w*e0v.z) + w*a0v.z;
        o0.w = v0.w*(1.0f - w*e0v.w) + w*a0v.w;
        o1.x = v1.x*(1.0f - w*e1v.x) + w*a1v.x;
        o1.y = v1.y*(1.0f - w*e1v.y) + w*a1v.y;
        o1.z = v1.z*(1.0f - w*e1v.z) + w*a1v.z;
        o1.w = v1.w*(1.0f - w*e1v.w) + w*a1v.w;
        float4* q = (float4*)(outM + base + (size_t)(it*32 + rowp)*M) + lane8*2;
        __stcs(q,     o0);
        __stcs(q + 1, o1);
    }
}

// ---------------------------------------------------------------------------
// Fixup + LSTM: gates = gatesT + M_read @ W_mid; h_new/c_new (4 h per block)
// ---------------------------------------------------------------------------
__device__ void fixup_dev(int blk, const float* __restrict__ W_ih,
                          const float* __restrict__ c,
                          float* __restrict__ out_h, float* __restrict__ out_c)
{
    __shared__ float Wm[16][65];
    __shared__ float Mr[64][65];
    int t = threadIdx.x;
    int hbase = blk * 4;

    {
        int r = t >> 4;
        int off = (t & 15) * 4;
        int gate = r >> 2, hloc = r & 3;
        float4 v = *(const float4*)(W_ih + (size_t)(gate*H + hbase + hloc)*(IN_DIM + M) + IN_DIM + off);
        Wm[r][off+0]=v.x; Wm[r][off+1]=v.y; Wm[r][off+2]=v.z; Wm[r][off+3]=v.w;
    }
    {
        int row = t >> 2;
        int col = (t & 3) * 16;
        const float4* src = (const float4*)(g_Mread + (size_t)row*M + col);
        float4 v0 = src[0], v1 = src[1], v2 = src[2], v3 = src[3];
        Mr[row][col+ 0]=v0.x; Mr[row][col+ 1]=v0.y; Mr[row][col+ 2]=v0.z; Mr[row][col+ 3]=v0.w;
        Mr[row][col+ 4]=v1.x; Mr[row][col+ 5]=v1.y; Mr[row][col+ 6]=v1.z; Mr[row][col+ 7]=v1.w;
        Mr[row][col+ 8]=v2.x; Mr[row][col+ 9]=v2.y; Mr[row][col+10]=v2.z; Mr[row][col+11]=v2.w;
        Mr[row][col+12]=v3.x; Mr[row][col+13]=v3.y; Mr[row][col+14]=v3.z; Mr[row][col+15]=v3.w;
    }
    __syncthreads();

    int b = t & 63;
    int hloc = t >> 6;
    int hh = hbase + hloc;

    float acc[4];
    #pragma unroll
    for (int g4 = 0; g4 < 4; g4++)
        acc[g4] = g_gatesT[(size_t)(g4*H + hh)*B + b];
    #pragma unroll 8
    for (int k = 0; k < M; k++) {
        float m = Mr[b][k];
        #pragma unroll
        for (int g4 = 0; g4 < 4; g4++) acc[g4] += m * Wm[g4*4 + hloc][k];
    }

    float cn = sigf(acc[1]) * c[(size_t)b*H + hh] + sigf(acc[0]) * tanhf(acc[2]);
    float hn = sigf(acc[3]) * tanhf(cn);
    out_c[(size_t)b*H + hh] = cn;
    out_h[(size_t)b*H + hh] = hn;

    __threadfence();
    __syncthreads();
    if (t == 0) atomicAdd(&ctrC, 1);
}

// ===========================================================================
// K1: ctrl(all) [0,64) | gemm [64,128) | dot(read) b0-31 fwd [128, 128+2048)
// ===========================================================================
__global__ void __launch_bounds__(256) k1_kernel(
    const float* __restrict__ Mem, const float* __restrict__ inp,
    const float* __restrict__ h,
    const float* __restrict__ W_ih, const float* __restrict__ b_ih,
    const float* __restrict__ W_hh, const float* __restrict__ b_hh,
    const float* __restrict__ kw, const float* __restrict__ kb,
    const float* __restrict__ cw, const float* __restrict__ cb,
    const float* __restrict__ sw, const float* __restrict__ sb)
{
    int bid = blockIdx.x;
    if (bid < B) {
        if (threadIdx.x == 0) fD[bid] = 0;            // reset K5/K6 flags
        controller_dev(bid, h, kw, kb, cw, cb, sw, sb, nullptr, nullptr);
        release(&fA[bid]);
        return;
    }
    if (bid < 2*B) {
        gemm_partial(bid - B, inp, h, W_ih, b_ih, W_hh, b_hh);
        return;
    }
    int idx = bid - 2*B;
    dot_tile(Mem, idx >> 6, idx & 63, fA);
}

// ===========================================================================
// K2: addr(0-31) [0,32) | mread(0-31) REV [32,2080) | dot(32-63) FWD [2080,4128)
// ===========================================================================
__global__ void __launch_bounds__(256) k2_kernel(
    const float* __restrict__ Mem,
    const float* __restrict__ rhead_prev, float* __restrict__ out_r)
{
    int bid = blockIdx.x;
    if (bid < HB) {
        int b = bid;
        if (threadIdx.x == 0) { fA[b] = 0; fA[b + HB] = 0; }   // reset K1 flags
        address_dev(b, rhead_prev, out_r);
        release(&fB[b]);
        return;
    }
    if (bid < HB + 2048) {
        int idx = bid - HB;
        int b  = (HB - 1) - (idx >> 6);      // reversed over half 0
        int xt = 63 - (idx & 63);
        mread_tile(Mem, out_r, b, xt);
        return;
    }
    int idx = bid - (HB + 2048);
    dot_tile(Mem, HB + (idx >> 6), idx & 63, nullptr);   // no spin: ctrl done in K1
}

// ===========================================================================
// K3: addr(32-63) [0,32) | mread(32-63) REV [32, 2080)
// ===========================================================================
__global__ void __launch_bounds__(256) k3_kernel(
    const float* __restrict__ Mem,
    const float* __restrict__ rhead_prev, float* __restrict__ out_r)
{
    int bid = blockIdx.x;
    if (bid < HB) {
        int b = HB + bid;
        address_dev(b, rhead_prev, out_r);
        release(&fB[b]);
        return;
    }
    int idx = bid - HB;
    int b  = HB + (HB - 1) - (idx >> 6);     // reversed over half 1
    int xt = 63 - (idx & 63);
    mread_tile(Mem, out_r, b, xt);
}

// ===========================================================================
// K4: fixup [0,128) | ctrlW [128,192) | dotW(32-63) FWD [192, 2240)
// ===========================================================================
__global__ void __launch_bounds__(256) k4_kernel(
    const float* __restrict__ Mem,
    const float* __restrict__ W_ih, const float* __restrict__ c,
    float* __restrict__ out_h, float* __restrict__ out_c,
    const float* __restrict__ wk_w, const float* __restrict__ wk_b,
    const float* __restrict__ wc_w, const float* __restrict__ wc_b,
    const float* __restrict__ ws_w, const float* __restrict__ ws_b,
    const float* __restrict__ w_w,  const float* __restrict__ w_b)
{
    int bid = blockIdx.x;
    if (bid < 128) {
        if (threadIdx.x == 0 && bid < B) { fB[bid] = 0; mcnt[bid] = 0; }  // reset K2/K3
        fixup_dev(bid, W_ih, c, out_h, out_c);
        return;
    }
    if (bid < 192) {
        int b = bid - 128;
        spin_count(&ctrC, 128);
        controller_dev(b, out_h, wk_w, wk_b, wc_w, wc_b, ws_w, ws_b, w_w, w_b);
        release(&fC[b]);
        return;
    }
    int idx = bid - 192;
    dot_tile(Mem, HB + (idx >> 6), idx & 63, fC);    // half 1, fwd (L2 from K3)
}

// ===========================================================================
// K5: addrW(32-63) [0,32) | mout(32-63) REV [32,2080) | dotW(0-31) FWD [2080,4128)
// ===========================================================================
__global__ void __launch_bounds__(256) k5_kernel(
    const float* __restrict__ Mem, const float* __restrict__ whead_prev,
    float* __restrict__ out_w, float* __restrict__ out_m)
{
    int bid = blockIdx.x;
    if (bid < HB) {
        int b = HB + bid;
        if (threadIdx.x == 0) { fC[b] = 0; fC[b - HB] = 0; }   // reset K4 flags
        address_dev(b, whead_prev, out_w);
        release(&fD[b]);
        return;
    }
    if (bid < HB + 2048) {
        int idx = bid - HB;
        int b  = HB + (HB - 1) - (idx >> 6);   // reversed over half 1 (L2 from K4)
        int xt = 63 - (idx & 63);
        mout_tile(Mem, out_w, out_m, b, xt);
        return;
    }
    int idx = bid - (HB + 2048);
    dot_tile(Mem, idx >> 6, idx & 63, nullptr);      // half 0, fwd, no spin (ctrlW done K4)
}

// ===========================================================================
// K6: addrW(0-31) [0,32) | mout(0-31) REV [32, 2080)
// ===========================================================================
__global__ void __launch_bounds__(256) k6_kernel(
    const float* __restrict__ Mem, const float* __restrict__ whead_prev,
    float* __restrict__ out_w, float* __restrict__ out_m)
{
    int bid = blockIdx.x;
    if (bid < HB) {
        int b = bid;
        if (threadIdx.x == 0 && b == 0) atomicExch(&ctrC, 0);  // reset K4 counter
        address_dev(b, whead_prev, out_w);
        release(&fD[b]);
        return;
    }
    int idx = bid - HB;
    int b  = (HB - 1) - (idx >> 6);          // reversed over half 0 (L2 from K5)
    int xt = 63 - (idx & 63);
    mout_tile(Mem, out_w, out_m, b, xt);
}

// ---------------------------------------------------------------------------
extern "C" void kernel_launch(void* const* d_in, const int* in_sizes, int n_in,
                              void* d_out, int out_size)
{
    const float* inp    = (const float*)d_in[0];
    const float* h      = (const float*)d_in[1];
    const float* c      = (const float*)d_in[2];
    const float* rhead  = (const float*)d_in[3];
    const float* whead  = (const float*)d_in[4];
    const float* mem    = (const float*)d_in[5];
    const float* W_ih   = (const float*)d_in[6];
    const float* b_ih   = (const float*)d_in[7];
    const float* W_hh   = (const float*)d_in[8];
    const float* b_hh   = (const float*)d_in[9];
    const float* rk_w   = (const float*)d_in[10];
    const float* rk_b   = (const float*)d_in[11];
    const float* rc_w   = (const float*)d_in[12];
    const float* rc_b   = (const float*)d_in[13];
    const float* rs_w   = (const float*)d_in[14];
    const float* rs_b   = (const float*)d_in[15];
    const float* wk_w   = (const float*)d_in[16];
    const float* wk_b   = (const float*)d_in[17];
    const float* wc_w   = (const float*)d_in[18];
    const float* wc_b   = (const float*)d_in[19];
    const float* ws_w   = (const float*)d_in[20];
    const float* ws_b   = (const float*)d_in[21];
    const float* w_w    = (const float*)d_in[22];
    const float* w_b    = (const float*)d_in[23];

    float* out   = (float*)d_out;
    float* out_h = out;
    float* out_c = out + OUT_C_OFF;
    float* out_r = out + OUT_R_OFF;
    float* out_w = out + OUT_W_OFF;
    float* out_m = out + OUT_M_OFF;

    k1_kernel<<<2*B + 2048, 256>>>(mem, inp, h, W_ih, b_ih, W_hh, b_hh,
                                   rk_w, rk_b, rc_w, rc_b, rs_w, rs_b);
    k2_kernel<<<HB + 4096, 256>>>(mem, rhead, out_r);
    k3_kernel<<<HB + 2048, 256>>>(mem, rhead, out_r);
    k4_kernel<<<192 + 2048, 256>>>(mem, W_ih, c, out_h, out_c,
                                   wk_w, wk_b, wc_w, wc_b, ws_w, ws_b,
                                   w_w, w_b);
    k5_kernel<<<HB + 4096, 256>>>(mem, whead, out_w, out_m);
    k6_kernel<<<HB + 2048, 256>>>(mem, whead, out_w, out_m);
}